// round 16
// baseline (speedup 1.0000x reference)
#include <cuda_runtime.h>
#include <cstdint>

// Problem constants
#define BB 64
#define HH 1024
#define II 512
#define MIN_TAU 1e-3f
#define LOG2E 1.4426950408889634f

// 296 CTAs = exactly 2 resident CTAs on every one of 148 SMs.
// ONE GLOBAL tile pool over all 8192 (og, b) tiles, og-major:
//   tile t: og = t >> 6, b = t & 63. CHUNK=2 aligned grabs never straddle
//   an og boundary. Every CTA drains the same pool -> end imbalance <= ~2
//   tiles (the per-og pools of R14/15 stranded the 3-sibling CTAs idle for
//   the last third: utilization 86.5%).
#define OW 8
#define NWARPS 9
#define OGROUPS (HH / OW)    // 128
#define NTILES (OGROUPS * BB)  // 8192
#define NCTAS 296
#define STAGES 3
#define CHUNK 2

// SMEM layout (dynamic) — R9-proven stage: 32KB gumbel + 4KB h_prev.
#define G_BYTES (OW * HH * 4)            // 32768
#define H_BYTES (HH * 4)                 // 4096
#define STAGE_BYTES (G_BYTES + H_BYTES)  // 36864
#define FULL_OFF (STAGES * STAGE_BYTES)  // 110592
#define EMPTY_OFF (FULL_OFF + STAGES * 8)
#define BIDX_OFF (EMPTY_OFF + STAGES * 8)      // int per stage: tile idx (or -1)
#define SMEM_BYTES (BIDX_OFF + STAGES * 4)     // 110652 -> 2 CTAs/SM

// Pool state. Zero at module load; the LAST of the 296 producers restores
// both to zero before exiting -> clean state for every graph replay, no
// prologue kernel.
__device__ int g_ctr;
__device__ int g_done;

static __device__ __forceinline__ uint32_t s2u(const void* p) {
    uint32_t a;
    asm("{ .reg .u64 t; cvta.to.shared.u64 t, %1; cvt.u32.u64 %0, t; }"
        : "=r"(a) : "l"(p));
    return a;
}

static __device__ __forceinline__ void mbar_init(uint32_t mbar, uint32_t cnt) {
    asm volatile("mbarrier.init.shared.b64 [%0], %1;" :: "r"(mbar), "r"(cnt) : "memory");
}

static __device__ __forceinline__ void mbar_expect_tx(uint32_t mbar, uint32_t bytes) {
    asm volatile("mbarrier.arrive.expect_tx.shared.b64 _, [%0], %1;"
                 :: "r"(mbar), "r"(bytes) : "memory");
}

static __device__ __forceinline__ void mbar_arrive(uint32_t mbar) {
    asm volatile("mbarrier.arrive.release.cta.shared::cta.b64 _, [%0];"
                 :: "r"(mbar) : "memory");
}

static __device__ __forceinline__ void mbar_wait(uint32_t mbar, uint32_t parity) {
    uint32_t done;
    asm volatile(
        "{\n\t.reg .pred p;\n\t"
        "mbarrier.try_wait.parity.acquire.cta.shared::cta.b64 p, [%1], %2;\n\t"
        "selp.b32 %0, 1, 0, p;\n\t}"
        : "=r"(done) : "r"(mbar), "r"(parity) : "memory");
    if (!done) {
        asm volatile(
            "{\n\t.reg .pred P1;\n\t"
            "WL_%=:\n\t"
            "mbarrier.try_wait.parity.acquire.cta.shared::cta.b64 P1, [%0], %1, 0x989680;\n\t"
            "@P1 bra.uni WD_%=;\n\t"
            "bra.uni WL_%=;\n\t"
            "WD_%=:\n\t}"
            :: "r"(mbar), "r"(parity) : "memory");
    }
}

static __device__ __forceinline__ void bulk_copy(uint32_t dst_smem, const void* src,
                                                 uint32_t bytes, uint32_t mbar) {
    asm volatile(
        "cp.async.bulk.shared::cta.global.mbarrier::complete_tx::bytes [%0], [%1], %2, [%3];"
        :: "r"(dst_smem), "l"(src), "r"(bytes), "r"(mbar) : "memory");
}

static __device__ __forceinline__ void fence_async_smem() {
    asm volatile("fence.proxy.async.shared::cta;" ::: "memory");
}

static __device__ __forceinline__ float ex2(float x) {
    float y;
    asm("ex2.approx.ftz.f32 %0, %1;" : "=f"(y) : "f"(x));
    return y;
}

// Fused ReservoirRNNCell step — R15 pipeline (3-stage ring, ONE 32KB gumbel
// + 4KB h_prev bulk copy per stage, dedicated producer warp, per-stage
// full/empty barriers, self-restoring pool) with a GLOBAL og-crossing tile
// scheduler:
//   producer: grab 2 tiles via atomicAdd(&g_ctr, 2); per tile t: wait empty
//   (round>=1) -> fence -> STS t into bidx[st] (ordered by the expect_tx
//   arrive-release) -> 32KB gumbel[b, og*8:og*8+8, :] + 4KB h_prev[b, :].
//   Pool empty -> sentinel (-1) + plain release-arrive -> done-count; the
//   296th producer zeroes g_ctr/g_done.
//   consumers: wait full (acquire) -> t = bidx[st]; if og changed since the
//   last tile, reload the pre-scaled W_hh row (8x LDG.128, L2-resident),
//   W_ih row and bias (~300cyc per 2 tiles, paid from consumer slack);
//   consume -> arrive empty -> reduce/store.
// Every tile is computed identically by whichever CTA grabs it ->
// deterministic output. h_prev rides the TMA payload (consumer-loop LDG of
// it drained the pipeline in R10/R11). Softmax without max-subtraction is
// safe: logits bounded (~18.5); rel_err 3.4e-7 across all rounds.
__global__ __launch_bounds__(288, 2) void reservoir_cell_kernel(
    const float* __restrict__ x_t,         // (B, I)
    const float* __restrict__ h_prev,      // (B, H)
    const float* __restrict__ W_ih,        // (H, I)
    const float* __restrict__ b_ih,        // (H,)
    const float* __restrict__ W_hh,        // (H, H)
    const float* __restrict__ temperature, // scalar
    const float* __restrict__ gumbel,      // (B, H, H)
    float* __restrict__ out)               // (B, H)
{
    extern __shared__ float smem[];
    const uint32_t smem_u = s2u(smem);
    const uint32_t fullb  = smem_u + FULL_OFF;
    const uint32_t emptyb = smem_u + EMPTY_OFF;
    int* __restrict__ bidx = reinterpret_cast<int*>(
        reinterpret_cast<char*>(smem) + BIDX_OFF);

    const int tid  = threadIdx.x;
    const int w    = tid >> 5;
    const int lane = tid & 31;

    // ---- init barriers ----
    if (tid == 0) {
#pragma unroll
        for (int j = 0; j < STAGES; ++j) {
            mbar_init(fullb + 8u * j, 1);
            mbar_init(emptyb + 8u * j, OW);   // one arrive per consumer warp
        }
    }
    __syncthreads();   // the ONLY block-wide sync

    // ================= PRODUCER WARP (w == 8) =================
    if (w == 8) {
        if (lane == 0) {
            int st = 0, rnd = 0, rem = 0, tcur = 0;
            for (;;) {
                if (rem == 0) {
                    const int p = atomicAdd(&g_ctr, CHUNK);
                    if (p >= NTILES) {
                        // pool empty: sentinel on the current stage
                        if (rnd >= 1) {
                            mbar_wait(emptyb + 8u * st, (rnd - 1) & 1);
                            fence_async_smem();
                        }
                        bidx[st] = -1;
                        mbar_arrive(fullb + 8u * st);  // release: flips (no tx)

                        // ---- pool restore (no prologue kernel) ----
                        __threadfence();  // order our g_ctr add before g_done
                        const int d = atomicAdd(&g_done, 1);
                        if (d == NCTAS - 1) {   // last producer chip-wide
                            atomicExch(&g_ctr, 0);
                            atomicExch(&g_done, 0);
                        }
                        break;
                    }
                    tcur = p;
                    rem = CHUNK;
                }
                if (rnd >= 1) {
                    mbar_wait(emptyb + 8u * st, (rnd - 1) & 1);
                    fence_async_smem();
                }
                bidx[st] = tcur;   // ordered by the expect_tx arrive-release
                const int b   = tcur & (BB - 1);
                const int ogt = tcur >> 6;
                const uint32_t mb = fullb + 8u * st;
                mbar_expect_tx(mb, STAGE_BYTES);
                const float* gsrc = gumbel + ((size_t)b * HH + ogt * OW) * HH;
                bulk_copy(smem_u + st * STAGE_BYTES, gsrc, G_BYTES, mb);
                const float* hsrc = h_prev + (size_t)b * HH;
                bulk_copy(smem_u + st * STAGE_BYTES + G_BYTES, hsrc, H_BYTES, mb);
                --rem; ++tcur;
                if (++st == STAGES) { st = 0; ++rnd; }
            }
        }
        return;
    }

    // ================= CONSUMER WARPS (w == 0..7) =================
    const float inv_tau_l2e = LOG2E / fmaxf(temperature[0], MIN_TAU);

    // og-dependent per-warp state, (re)loaded on og change (<= once / 2 tiles)
    int cur_og = -1;
    float4 wp[8];    // W_hh row, pre-scaled by inv_tau*log2e
    float4 wih[4];   // W_ih row
    float bias = 0.0f;

    int st = 0;
    int parity = 0;   // stage st's k-th use has parity k&1
    for (;;) {
        mbar_wait(fullb + 8u * st, parity);
        const int t_idx = bidx[st];   // visible via acquire
        if (t_idx < 0) break;
        const int b   = t_idx & (BB - 1);
        const int ogt = t_idx >> 6;

        if (ogt != cur_og) {
            cur_og = ogt;
            const int o = ogt * OW + w;
            const float4* __restrict__ whr =
                reinterpret_cast<const float4*>(W_hh + (size_t)o * HH);
#pragma unroll
            for (int k = 0; k < 8; ++k) {
                float4 v = whr[lane + 32 * k];
                v.x *= inv_tau_l2e; v.y *= inv_tau_l2e;
                v.z *= inv_tau_l2e; v.w *= inv_tau_l2e;
                wp[k] = v;
            }
            const float4* __restrict__ wir =
                reinterpret_cast<const float4*>(W_ih + (size_t)o * II);
#pragma unroll
            for (int k = 0; k < 4; ++k) wih[k] = wir[lane + 32 * k];
            bias = b_ih[o];
        }

        // input contribution: x_t row LDG (L2-resident); latency hides under
        // the gumbel LDS/MUFU chain (ic only consumed at the reduction).
        const float4* __restrict__ xr =
            reinterpret_cast<const float4*>(x_t + (size_t)b * II);
        float ic = 0.0f;
#pragma unroll
        for (int k = 0; k < 4; ++k) {
            const float4 xv = xr[lane + 32 * k];
            ic = fmaf(xv.x, wih[k].x, ic);
            ic = fmaf(xv.y, wih[k].y, ic);
            ic = fmaf(xv.z, wih[k].z, ic);
            ic = fmaf(xv.w, wih[k].w, ic);
        }

        const float4* __restrict__ gs = reinterpret_cast<const float4*>(
            smem + (size_t)st * (STAGE_BYTES / 4) + (size_t)w * HH);
        const float4* __restrict__ hs = reinterpret_cast<const float4*>(
            smem + (size_t)st * (STAGE_BYTES / 4) + G_BYTES / 4);

        float s = 0.0f, t = 0.0f;
#pragma unroll
        for (int k = 0; k < 8; ++k) {
            const int idx = lane + 32 * k;
            const float4 g = gs[idx];
            const float4 h = hs[idx];
            float e;
            e = ex2(fmaf(g.x, LOG2E, wp[k].x)); s += e; t = fmaf(e, h.x, t);
            e = ex2(fmaf(g.y, LOG2E, wp[k].y)); s += e; t = fmaf(e, h.y, t);
            e = ex2(fmaf(g.z, LOG2E, wp[k].z)); s += e; t = fmaf(e, h.z, t);
            e = ex2(fmaf(g.w, LOG2E, wp[k].w)); s += e; t = fmaf(e, h.w, t);
        }

        // stage consumed into registers: signal the producer, move on.
        __syncwarp();
        if (lane == 0) mbar_arrive(emptyb + 8u * st);

        // warp reductions + output (overlaps the producer's refill)
#pragma unroll
        for (int off = 16; off > 0; off >>= 1) {
            s  += __shfl_xor_sync(0xffffffffu, s,  off);
            t  += __shfl_xor_sync(0xffffffffu, t,  off);
            ic += __shfl_xor_sync(0xffffffffu, ic, off);
        }
        if (lane == 0) {
            out[(size_t)b * HH + (ogt * OW + w)] = tanhf(ic + bias + t / s);
        }

        if (++st == STAGES) { st = 0; parity ^= 1; }
    }
}

extern "C" void kernel_launch(void* const* d_in, const int* in_sizes, int n_in,
                              void* d_out, int out_size) {
    // metadata order: x_t, h_prev, W_ih, b_ih, W_hh, temperature, gumbel_noise
    const float* x_t    = (const float*)d_in[0];
    const float* h_prev = (const float*)d_in[1];
    const float* W_ih   = (const float*)d_in[2];
    const float* b_ih   = (const float*)d_in[3];
    const float* W_hh   = (const float*)d_in[4];
    const float* temp   = (const float*)d_in[5];
    const float* gum    = (const float*)d_in[6];
    float* out = (float*)d_out;

    static bool attr_set = false;
    if (!attr_set) {
        cudaFuncSetAttribute(reservoir_cell_kernel,
                             cudaFuncAttributeMaxDynamicSharedMemorySize, SMEM_BYTES);
        attr_set = true;
    }

    // Single kernel node: the pool self-restores at the end of each launch.
    dim3 grid(NCTAS);              // 296 CTAs = exactly 2 per SM
    dim3 block(NWARPS * 32);       // 288 threads: 8 consumer + 1 producer warp
    reservoir_cell_kernel<<<grid, block, SMEM_BYTES>>>(
        x_t, h_prev, W_ih, b_ih, W_hh, temp, gum, out);
}

// round 17
// speedup vs baseline: 1.0471x; 1.0471x over previous
#include <cuda_runtime.h>
#include <cstdint>

// Problem constants
#define BB 64
#define HH 1024
#define II 512
#define MIN_TAU 1e-3f
#define LOG2E 1.4426950408889634f

// 296 CTAs = exactly 2 resident CTAs on every one of 148 SMs.
// STATIC EQUAL PARTITION of the 8192 (og, b) tiles, og-major
// (tile t: og = t >> 6, b = t & 63):
//   CTA bid owns tiles [bid*8192/296, (bid+1)*8192/296) -> 27 or 28
//   CONTIGUOUS tiles. Since 28 < 64, each CTA's range crosses at most ONE
//   og boundary -> at most one W_hh-row reload per CTA (vs every 2 tiles in
//   R16's global pool, which regressed). Perfect +-1-tile balance fixes the
//   R15 tail (86.5% utilization from unequal per-og sibling counts) with no
//   atomics, no pool-restore, no smem tile handoff: producer and consumers
//   walk the same statically-known tile sequence. Fully deterministic.
#define OW 8
#define NWARPS 9
#define OGROUPS (HH / OW)      // 128
#define NTILES (OGROUPS * BB)  // 8192
#define NCTAS 296
#define STAGES 3

// SMEM layout (dynamic) — R9-proven stage: 32KB gumbel + 4KB h_prev.
#define G_BYTES (OW * HH * 4)            // 32768
#define H_BYTES (HH * 4)                 // 4096
#define STAGE_BYTES (G_BYTES + H_BYTES)  // 36864
#define FULL_OFF (STAGES * STAGE_BYTES)  // 110592
#define EMPTY_OFF (FULL_OFF + STAGES * 8)
#define SMEM_BYTES (EMPTY_OFF + STAGES * 8)   // 110640 -> 2 CTAs/SM

static __device__ __forceinline__ uint32_t s2u(const void* p) {
    uint32_t a;
    asm("{ .reg .u64 t; cvta.to.shared.u64 t, %1; cvt.u32.u64 %0, t; }"
        : "=r"(a) : "l"(p));
    return a;
}

static __device__ __forceinline__ void mbar_init(uint32_t mbar, uint32_t cnt) {
    asm volatile("mbarrier.init.shared.b64 [%0], %1;" :: "r"(mbar), "r"(cnt) : "memory");
}

static __device__ __forceinline__ void mbar_expect_tx(uint32_t mbar, uint32_t bytes) {
    asm volatile("mbarrier.arrive.expect_tx.shared.b64 _, [%0], %1;"
                 :: "r"(mbar), "r"(bytes) : "memory");
}

static __device__ __forceinline__ void mbar_arrive(uint32_t mbar) {
    asm volatile("mbarrier.arrive.release.cta.shared::cta.b64 _, [%0];"
                 :: "r"(mbar) : "memory");
}

static __device__ __forceinline__ void mbar_wait(uint32_t mbar, uint32_t parity) {
    uint32_t done;
    asm volatile(
        "{\n\t.reg .pred p;\n\t"
        "mbarrier.try_wait.parity.acquire.cta.shared::cta.b64 p, [%1], %2;\n\t"
        "selp.b32 %0, 1, 0, p;\n\t}"
        : "=r"(done) : "r"(mbar), "r"(parity) : "memory");
    if (!done) {
        asm volatile(
            "{\n\t.reg .pred P1;\n\t"
            "WL_%=:\n\t"
            "mbarrier.try_wait.parity.acquire.cta.shared::cta.b64 P1, [%0], %1, 0x989680;\n\t"
            "@P1 bra.uni WD_%=;\n\t"
            "bra.uni WL_%=;\n\t"
            "WD_%=:\n\t}"
            :: "r"(mbar), "r"(parity) : "memory");
    }
}

static __device__ __forceinline__ void bulk_copy(uint32_t dst_smem, const void* src,
                                                 uint32_t bytes, uint32_t mbar) {
    asm volatile(
        "cp.async.bulk.shared::cta.global.mbarrier::complete_tx::bytes [%0], [%1], %2, [%3];"
        :: "r"(dst_smem), "l"(src), "r"(bytes), "r"(mbar) : "memory");
}

static __device__ __forceinline__ void fence_async_smem() {
    asm volatile("fence.proxy.async.shared::cta;" ::: "memory");
}

static __device__ __forceinline__ float ex2(float x) {
    float y;
    asm("ex2.approx.ftz.f32 %0, %1;" : "=f"(y) : "f"(x));
    return y;
}

// Fused ReservoirRNNCell step — warp-specialized TMA pipeline (R15 skeleton:
// 3-stage ring, ONE 32KB gumbel + 4KB h_prev bulk copy per stage — the
// proven optimal copy granularity — per-stage full (tx) / empty (8 arrivals)
// barriers, dedicated producer warp, consumers never wait on each other)
// over a static equal tile partition (see header comment).
// h_prev rides the TMA payload (consumer-loop LDG of it drained the
// pipeline in R10/R11). Softmax without max-subtraction is safe: logits
// bounded (~18.5 from Gumbel with u in [1e-8, 1-1e-8]); rel_err 3.4e-7
// across all rounds.
__global__ __launch_bounds__(288, 2) void reservoir_cell_kernel(
    const float* __restrict__ x_t,         // (B, I)
    const float* __restrict__ h_prev,      // (B, H)
    const float* __restrict__ W_ih,        // (H, I)
    const float* __restrict__ b_ih,        // (H,)
    const float* __restrict__ W_hh,        // (H, H)
    const float* __restrict__ temperature, // scalar
    const float* __restrict__ gumbel,      // (B, H, H)
    float* __restrict__ out)               // (B, H)
{
    extern __shared__ float smem[];
    const uint32_t smem_u = s2u(smem);
    const uint32_t fullb  = smem_u + FULL_OFF;
    const uint32_t emptyb = smem_u + EMPTY_OFF;

    // static contiguous tile range for this CTA (same formula in producer
    // and consumers -> no handoff needed)
    const int bid = blockIdx.x;
    const int t0 = (int)(((long long)bid * NTILES) / NCTAS);
    const int t1 = (int)(((long long)(bid + 1) * NTILES) / NCTAS);
    const int ntile = t1 - t0;   // 27 or 28

    const int tid  = threadIdx.x;
    const int w    = tid >> 5;
    const int lane = tid & 31;

    // ---- init barriers ----
    if (tid == 0) {
#pragma unroll
        for (int j = 0; j < STAGES; ++j) {
            mbar_init(fullb + 8u * j, 1);
            mbar_init(emptyb + 8u * j, OW);   // one arrive per consumer warp
        }
    }
    __syncthreads();   // the ONLY block-wide sync

    // ================= PRODUCER WARP (w == 8) =================
    if (w == 8) {
        if (lane == 0) {
            int st = 0, rnd = 0;
            for (int i = 0; i < ntile; ++i) {
                const int t = t0 + i;
                const int b   = t & (BB - 1);
                const int ogt = t >> 6;
                if (rnd >= 1) {
                    mbar_wait(emptyb + 8u * st, (rnd - 1) & 1);
                    fence_async_smem();
                }
                const uint32_t mb = fullb + 8u * st;
                mbar_expect_tx(mb, STAGE_BYTES);
                const float* gsrc = gumbel + ((size_t)b * HH + ogt * OW) * HH;
                bulk_copy(smem_u + st * STAGE_BYTES, gsrc, G_BYTES, mb);
                const float* hsrc = h_prev + (size_t)b * HH;
                bulk_copy(smem_u + st * STAGE_BYTES + G_BYTES, hsrc, H_BYTES, mb);
                if (++st == STAGES) { st = 0; ++rnd; }
            }
        }
        return;
    }

    // ================= CONSUMER WARPS (w == 0..7) =================
    const float inv_tau_l2e = LOG2E / fmaxf(temperature[0], MIN_TAU);

    // og-dependent per-warp state; reloaded at most ONCE mid-range (a
    // contiguous 28-tile og-major range crosses <= 1 og boundary).
    int cur_og = -1;
    float4 wp[8];    // W_hh row, pre-scaled by inv_tau*log2e
    float4 wih[4];   // W_ih row
    float bias = 0.0f;

    int st = 0;
    int parity = 0;   // stage st's k-th use has parity k&1
    for (int i = 0; i < ntile; ++i) {
        const int t = t0 + i;
        const int b   = t & (BB - 1);
        const int ogt = t >> 6;

        // og-state reload happens OUTSIDE the full-wait (we know the tile
        // sequence statically), so its L2 latency overlaps the wait.
        if (ogt != cur_og) {
            cur_og = ogt;
            const int o = ogt * OW + w;
            const float4* __restrict__ whr =
                reinterpret_cast<const float4*>(W_hh + (size_t)o * HH);
#pragma unroll
            for (int k = 0; k < 8; ++k) {
                float4 v = whr[lane + 32 * k];
                v.x *= inv_tau_l2e; v.y *= inv_tau_l2e;
                v.z *= inv_tau_l2e; v.w *= inv_tau_l2e;
                wp[k] = v;
            }
            const float4* __restrict__ wir =
                reinterpret_cast<const float4*>(W_ih + (size_t)o * II);
#pragma unroll
            for (int k = 0; k < 4; ++k) wih[k] = wir[lane + 32 * k];
            bias = b_ih[o];
        }

        // input contribution (L2-resident x_t) — issued before the wait so
        // its latency hides under it.
        const float4* __restrict__ xr =
            reinterpret_cast<const float4*>(x_t + (size_t)b * II);
        float ic = 0.0f;
#pragma unroll
        for (int k = 0; k < 4; ++k) {
            const float4 xv = xr[lane + 32 * k];
            ic = fmaf(xv.x, wih[k].x, ic);
            ic = fmaf(xv.y, wih[k].y, ic);
            ic = fmaf(xv.z, wih[k].z, ic);
            ic = fmaf(xv.w, wih[k].w, ic);
        }

        mbar_wait(fullb + 8u * st, parity);

        const float4* __restrict__ gs = reinterpret_cast<const float4*>(
            smem + (size_t)st * (STAGE_BYTES / 4) + (size_t)w * HH);
        const float4* __restrict__ hs = reinterpret_cast<const float4*>(
            smem + (size_t)st * (STAGE_BYTES / 4) + G_BYTES / 4);

        float s = 0.0f, t_acc = 0.0f;
#pragma unroll
        for (int k = 0; k < 8; ++k) {
            const int idx = lane + 32 * k;
            const float4 g = gs[idx];
            const float4 h = hs[idx];
            float e;
            e = ex2(fmaf(g.x, LOG2E, wp[k].x)); s += e; t_acc = fmaf(e, h.x, t_acc);
            e = ex2(fmaf(g.y, LOG2E, wp[k].y)); s += e; t_acc = fmaf(e, h.y, t_acc);
            e = ex2(fmaf(g.z, LOG2E, wp[k].z)); s += e; t_acc = fmaf(e, h.z, t_acc);
            e = ex2(fmaf(g.w, LOG2E, wp[k].w)); s += e; t_acc = fmaf(e, h.w, t_acc);
        }

        // stage consumed into registers: signal the producer, move on.
        __syncwarp();
        if (lane == 0) mbar_arrive(emptyb + 8u * st);

        // warp reductions + output (overlaps the producer's refill)
#pragma unroll
        for (int off = 16; off > 0; off >>= 1) {
            s     += __shfl_xor_sync(0xffffffffu, s,     off);
            t_acc += __shfl_xor_sync(0xffffffffu, t_acc, off);
            ic    += __shfl_xor_sync(0xffffffffu, ic,    off);
        }
        if (lane == 0) {
            out[(size_t)b * HH + (ogt * OW + w)] = tanhf(ic + bias + t_acc / s);
        }

        if (++st == STAGES) { st = 0; parity ^= 1; }
    }
}

extern "C" void kernel_launch(void* const* d_in, const int* in_sizes, int n_in,
                              void* d_out, int out_size) {
    // metadata order: x_t, h_prev, W_ih, b_ih, W_hh, temperature, gumbel_noise
    const float* x_t    = (const float*)d_in[0];
    const float* h_prev = (const float*)d_in[1];
    const float* W_ih   = (const float*)d_in[2];
    const float* b_ih   = (const float*)d_in[3];
    const float* W_hh   = (const float*)d_in[4];
    const float* temp   = (const float*)d_in[5];
    const float* gum    = (const float*)d_in[6];
    float* out = (float*)d_out;

    static bool attr_set = false;
    if (!attr_set) {
        cudaFuncSetAttribute(reservoir_cell_kernel,
                             cudaFuncAttributeMaxDynamicSharedMemorySize, SMEM_BYTES);
        attr_set = true;
    }

    dim3 grid(NCTAS);              // 296 CTAs = exactly 2 per SM
    dim3 block(NWARPS * 32);       // 288 threads: 8 consumer + 1 producer warp
    reservoir_cell_kernel<<<grid, block, SMEM_BYTES>>>(
        x_t, h_prev, W_ih, b_ih, W_hh, temp, gum, out);
}